// round 11
// baseline (speedup 1.0000x reference)
#include <cuda_runtime.h>
#include <cuda_bf16.h>

// ResidualAverageBlock, fused persistent kernel, high-occupancy variant.
//   Phase A: s[32] = sum_n w_n * x_n ; sw = sum_n w_n   (per-block partials)
//   grid-barrier (replay-safe)
//   Phase B (last block): h = relu((s@Win^T)/sw); x_ = h@Wout^T
//   Phase C (all blocks): out = x + broadcast(x_), LIFO over this block's own
//            phase-A rows (L2/L1 temporal reuse), evict-first loads/stores.

#define BLOCKS_A 888
#define TPB_A    256
#define WARPS_A  (TPB_A / 32)             // 8
#define TOTAL_WARPS (BLOCKS_A * WARPS_A)  // 7104

__device__ float g_part[33 * BLOCKS_A];   // [c][b]
__device__ float g_res[32];
__device__ int   g_arrive  = 0;           // reset by last block each run
__device__ int   g_release = 0;           // monotone across graph replays

__global__ __launch_bounds__(TPB_A, 6)
void fused_kernel(const float* __restrict__ x, const float* __restrict__ w,
                  const float* __restrict__ Win, const float* __restrict__ Wout,
                  float* __restrict__ out, int N)
{
    const int tid  = threadIdx.x;
    const int lane = tid & 31;
    const int warp = tid >> 5;
    const int sub  = lane & 7;     // column group: cols 4*sub .. 4*sub+3
    const int rg   = lane >> 3;    // row offset within 4-row group

    __shared__ float4 sh4[WARPS_A][8];
    __shared__ float  shw[WARPS_A];
    __shared__ float  red[33][8];
    __shared__ float  s_[33];
    __shared__ float  h_[128];
    __shared__ float4 r4s[8];
    __shared__ int    sh_last, sh_r0;

    const int R = (N + TOTAL_WARPS - 1) / TOTAL_WARPS;    // 141 rows per warp

    // ---------------- Phase A: weighted column reduce ----------------
    {
        const float4* __restrict__ x4 = reinterpret_cast<const float4*>(x);
        const int gw = blockIdx.x * WARPS_A + warp;
        int row      = gw * R;
        const int r1 = min(row + R, N);

        float4 acc = make_float4(0.f, 0.f, 0.f, 0.f);
        float  accw = 0.f;

        // one LDG.128 covers 4 rows per warp; 16 rows / iteration
        for (; row + 16 <= r1; row += 16) {
            #pragma unroll
            for (int u = 0; u < 4; ++u) {
                int r = row + rg + (u << 2);
                float  wv = __ldg(&w[r]);
                float4 xv = __ldg(&x4[r * 8 + sub]);
                acc.x = fmaf(wv, xv.x, acc.x);
                acc.y = fmaf(wv, xv.y, acc.y);
                acc.z = fmaf(wv, xv.z, acc.z);
                acc.w = fmaf(wv, xv.w, acc.w);
                accw += wv;
            }
        }
        if (row < r1) {
            #pragma unroll
            for (int u = 0; u < 4; ++u) {
                int r = row + rg + (u << 2);
                if (r < r1) {
                    float  wv = __ldg(&w[r]);
                    float4 xv = __ldg(&x4[r * 8 + sub]);
                    acc.x = fmaf(wv, xv.x, acc.x);
                    acc.y = fmaf(wv, xv.y, acc.y);
                    acc.z = fmaf(wv, xv.z, acc.z);
                    acc.w = fmaf(wv, xv.w, acc.w);
                    accw += wv;
                }
            }
        }

        // reduce over rg (lanes differing in bits 3,4); rows distinct per thread,
        // duplicated only across sub -> accw needs no correction.
        #pragma unroll
        for (int off = 8; off < 32; off <<= 1) {
            acc.x += __shfl_xor_sync(0xFFFFFFFFu, acc.x, off);
            acc.y += __shfl_xor_sync(0xFFFFFFFFu, acc.y, off);
            acc.z += __shfl_xor_sync(0xFFFFFFFFu, acc.z, off);
            acc.w += __shfl_xor_sync(0xFFFFFFFFu, acc.w, off);
            accw  += __shfl_xor_sync(0xFFFFFFFFu, accw,  off);
        }
        if (lane < 8)  sh4[warp][lane] = acc;
        if (lane == 0) shw[warp] = accw;
    }
    __syncthreads();

    if (tid < 32) {
        float v = 0.f;
        #pragma unroll
        for (int q = 0; q < WARPS_A; ++q)
            v += reinterpret_cast<const float*>(&sh4[q][tid >> 2])[tid & 3];
        g_part[tid * BLOCKS_A + blockIdx.x] = v;
    } else if (tid == 32) {
        float v = 0.f;
        #pragma unroll
        for (int q = 0; q < WARPS_A; ++q) v += shw[q];
        g_part[32 * BLOCKS_A + blockIdx.x] = v;
    }
    if (tid < 33) __threadfence();     // push g_part to L2 before arriving
    __syncthreads();

    // ---------------- grid barrier (replay-safe) ----------------
    if (tid == 0) {
        sh_r0 = *(volatile int*)&g_release;
        __threadfence();
        int t = atomicAdd(&g_arrive, 1);
        sh_last = (t == BLOCKS_A - 1);
    }
    __syncthreads();

    if (sh_last) {
        // ---------------- Phase B: finish reduce + tiny MLP ----------------
        {   // cols 0..31: 8 sub-reducers each (all 256 threads)
            int c = tid >> 3, k = tid & 7;
            float a = 0.f;
            #pragma unroll 4
            for (int b = k; b < BLOCKS_A; b += 8)
                a += __ldcg(&g_part[c * BLOCKS_A + b]);
            red[c][k] = a;
        }
        if (tid < 8) {  // col 32 (sum of weights)
            float a = 0.f;
            #pragma unroll 4
            for (int b = tid; b < BLOCKS_A; b += 8)
                a += __ldcg(&g_part[32 * BLOCKS_A + b]);
            red[32][tid] = a;
        }
        __syncthreads();
        if (tid < 33) {
            float a = 0.f;
            #pragma unroll
            for (int k = 0; k < 8; ++k) a += red[tid][k];
            s_[tid] = a;
        }
        __syncthreads();
        if (tid < 128) {
            float inv = 1.f / s_[32];
            float d = 0.f;
            #pragma unroll
            for (int i = 0; i < 32; ++i) d = fmaf(s_[i], Win[tid * 32 + i], d);
            h_[tid] = fmaxf(d * inv, 0.f);
        }
        __syncthreads();
        if (tid < 32) {
            float d = 0.f;
            #pragma unroll
            for (int j = 0; j < 128; ++j) d = fmaf(h_[j], Wout[tid * 128 + j], d);
            g_res[tid] = d;
            __threadfence();
        }
        __syncthreads();
        if (tid == 0) {
            g_arrive = 0;                      // reset for next graph replay
            __threadfence();
            atomicAdd(&g_release, 1);          // monotone release
        }
    } else {
        if (tid == 0) {
            while (*(volatile int*)&g_release == sh_r0) __nanosleep(64);
        }
        __syncthreads();
        __threadfence();
    }

    // ---------------- Phase C: out = x + broadcast(x_) ----------------
    // LIFO over the SAME rows this block reduced in phase A; evict-first
    // loads (last use) and stores (don't pollute L2 for other blocks).
    if (tid < 8) r4s[tid] = __ldcg(reinterpret_cast<const float4*>(g_res) + tid);
    __syncthreads();

    {
        const float4* __restrict__ xr = reinterpret_cast<const float4*>(x);
        float4* __restrict__ ow       = reinterpret_cast<float4*>(out);
        const int n4     = N * 8;
        const int chunkC = R * WARPS_A * 8;                 // same rows as phase A
        const int start  = blockIdx.x * chunkC;
        const int end    = min(start + chunkC, n4);
        const int count  = max(end - start, 0);
        const int nFull  = count / TPB_A;
        const int rem    = count - nFull * TPB_A;

        const float4 rv = r4s[tid & 7];   // i%8 == tid%8 (start, TPB mult of 8)

        // partial strip (highest addresses) first
        if (rem && tid < rem) {
            int i = start + nFull * TPB_A + tid;
            float4 v = __ldcs(&xr[i]);
            v.x += rv.x; v.y += rv.y; v.z += rv.z; v.w += rv.w;
            __stcs(&ow[i], v);
        }

        int k = nFull;
        for (; k >= 4; k -= 4) {
            int ib = start + (k - 4) * TPB_A + tid;
            float4 v0 = __ldcs(&xr[ib + 3 * TPB_A]);
            float4 v1 = __ldcs(&xr[ib + 2 * TPB_A]);
            float4 v2 = __ldcs(&xr[ib + 1 * TPB_A]);
            float4 v3 = __ldcs(&xr[ib + 0 * TPB_A]);
            v0.x += rv.x; v0.y += rv.y; v0.z += rv.z; v0.w += rv.w;
            v1.x += rv.x; v1.y += rv.y; v1.z += rv.z; v1.w += rv.w;
            v2.x += rv.x; v2.y += rv.y; v2.z += rv.z; v2.w += rv.w;
            v3.x += rv.x; v3.y += rv.y; v3.z += rv.z; v3.w += rv.w;
            __stcs(&ow[ib + 3 * TPB_A], v0);
            __stcs(&ow[ib + 2 * TPB_A], v1);
            __stcs(&ow[ib + 1 * TPB_A], v2);
            __stcs(&ow[ib + 0 * TPB_A], v3);
        }
        for (; k >= 1; --k) {
            int i = start + (k - 1) * TPB_A + tid;
            float4 v = __ldcs(&xr[i]);
            v.x += rv.x; v.y += rv.y; v.z += rv.z; v.w += rv.w;
            __stcs(&ow[i], v);
        }
    }
}

extern "C" void kernel_launch(void* const* d_in, const int* in_sizes, int n_in,
                              void* d_out, int out_size)
{
    const float* x    = (const float*)d_in[0];   // [N,32]
    const float* w    = (const float*)d_in[1];   // [N,1]
    const float* Win  = (const float*)d_in[2];   // [128,32]
    const float* Wout = (const float*)d_in[3];   // [32,128]
    float* out        = (float*)d_out;           // [N,32]

    const int N = in_sizes[1];                   // 1,000,000

    fused_kernel<<<BLOCKS_A, TPB_A>>>(x, w, Win, Wout, out, N);
}

// round 12
// speedup vs baseline: 1.0832x; 1.0832x over previous
#include <cuda_runtime.h>
#include <cuda_bf16.h>

// ResidualAverageBlock, fused persistent kernel.
//   Phase A: s[32] = sum_n w_n * x_n ; sw = sum_n w_n   (per-block partials)
//            -- w vectorized (LDG.128), 32 rows per warp-iteration
//   grid-barrier (replay-safe)
//   Phase B (last block): h = relu((s@Win^T)/sw); x_ = h@Wout^T
//   Phase C (all blocks): out = x + broadcast(x_), LIFO over this block's own
//            phase-A rows, evict-first loads/stores.

#define NBLK  608                          // 4 per SM x 152 SMs
#define TPB   256
#define NWARP (TPB / 32)                   // 8
#define TOTW  (NBLK * NWARP)               // 4864

__device__ float g_part[33 * NBLK];        // [c][b]
__device__ float g_res[32];
__device__ int   g_arrive  = 0;            // reset by last block each run
__device__ int   g_release = 0;            // monotone across graph replays

__global__ __launch_bounds__(TPB, 4)
void fused_kernel(const float* __restrict__ x, const float* __restrict__ w,
                  const float* __restrict__ Win, const float* __restrict__ Wout,
                  float* __restrict__ out, int N)
{
    const int tid  = threadIdx.x;
    const int lane = tid & 31;
    const int warp = tid >> 5;
    const int sub  = lane & 7;     // column group: cols 4*sub .. 4*sub+3
    const int rg   = lane >> 3;    // row group within warp

    __shared__ float4 sh4[NWARP][8];
    __shared__ float  shw[NWARP];
    __shared__ float  red[33][8];
    __shared__ float  s_[33];
    __shared__ float  h_[128];
    __shared__ float4 r4s[8];
    __shared__ int    sh_last, sh_r0;

    const int R = (N + TOTW - 1) / TOTW;    // 206 rows per warp

    // ---------------- Phase A: weighted column reduce ----------------
    {
        const float4* __restrict__ x4 = reinterpret_cast<const float4*>(x);
        const float4* __restrict__ w4 = reinterpret_cast<const float4*>(w);
        const int gw = blockIdx.x * NWARP + warp;
        int row      = gw * R;
        const int r1 = min(row + R, N);

        float4 acc = make_float4(0.f, 0.f, 0.f, 0.f);
        float  accw = 0.f;

        // 32 rows per iter. Thread (rg,sub) owns rows row+4rg..+3 and
        // row+16+4rg..+3, columns 4sub..4sub+3. All 10 loads are LDG.128
        // and front-batchable (no consumer between them).
        for (; row + 32 <= r1; row += 32) {
            const int rb = row >> 2;
            float4 wa = __ldg(&w4[rb + rg]);
            float4 wb = __ldg(&w4[rb + 4 + rg]);
            float4 xv0 = __ldg(&x4[(row +      4*rg + 0) * 8 + sub]);
            float4 xv1 = __ldg(&x4[(row +      4*rg + 1) * 8 + sub]);
            float4 xv2 = __ldg(&x4[(row +      4*rg + 2) * 8 + sub]);
            float4 xv3 = __ldg(&x4[(row +      4*rg + 3) * 8 + sub]);
            float4 xv4 = __ldg(&x4[(row + 16 + 4*rg + 0) * 8 + sub]);
            float4 xv5 = __ldg(&x4[(row + 16 + 4*rg + 1) * 8 + sub]);
            float4 xv6 = __ldg(&x4[(row + 16 + 4*rg + 2) * 8 + sub]);
            float4 xv7 = __ldg(&x4[(row + 16 + 4*rg + 3) * 8 + sub]);

            acc.x = fmaf(wa.x, xv0.x, acc.x); acc.y = fmaf(wa.x, xv0.y, acc.y);
            acc.z = fmaf(wa.x, xv0.z, acc.z); acc.w = fmaf(wa.x, xv0.w, acc.w);
            acc.x = fmaf(wa.y, xv1.x, acc.x); acc.y = fmaf(wa.y, xv1.y, acc.y);
            acc.z = fmaf(wa.y, xv1.z, acc.z); acc.w = fmaf(wa.y, xv1.w, acc.w);
            acc.x = fmaf(wa.z, xv2.x, acc.x); acc.y = fmaf(wa.z, xv2.y, acc.y);
            acc.z = fmaf(wa.z, xv2.z, acc.z); acc.w = fmaf(wa.z, xv2.w, acc.w);
            acc.x = fmaf(wa.w, xv3.x, acc.x); acc.y = fmaf(wa.w, xv3.y, acc.y);
            acc.z = fmaf(wa.w, xv3.z, acc.z); acc.w = fmaf(wa.w, xv3.w, acc.w);
            acc.x = fmaf(wb.x, xv4.x, acc.x); acc.y = fmaf(wb.x, xv4.y, acc.y);
            acc.z = fmaf(wb.x, xv4.z, acc.z); acc.w = fmaf(wb.x, xv4.w, acc.w);
            acc.x = fmaf(wb.y, xv5.x, acc.x); acc.y = fmaf(wb.y, xv5.y, acc.y);
            acc.z = fmaf(wb.y, xv5.z, acc.z); acc.w = fmaf(wb.y, xv5.w, acc.w);
            acc.x = fmaf(wb.z, xv6.x, acc.x); acc.y = fmaf(wb.z, xv6.y, acc.y);
            acc.z = fmaf(wb.z, xv6.z, acc.z); acc.w = fmaf(wb.z, xv6.w, acc.w);
            acc.x = fmaf(wb.w, xv7.x, acc.x); acc.y = fmaf(wb.w, xv7.y, acc.y);
            acc.z = fmaf(wb.w, xv7.z, acc.z); acc.w = fmaf(wb.w, xv7.w, acc.w);

            accw += ((wa.x + wa.y) + (wa.z + wa.w))
                  + ((wb.x + wb.y) + (wb.z + wb.w));
        }
        // tail: 4-rows-at-a-time collective, rows row+rg
        for (; row < r1; row += 4) {
            int rr = row + rg;
            if (rr < r1) {
                float  wv = __ldg(&w[rr]);
                float4 xv = __ldg(&x4[rr * 8 + sub]);
                acc.x = fmaf(wv, xv.x, acc.x);
                acc.y = fmaf(wv, xv.y, acc.y);
                acc.z = fmaf(wv, xv.z, acc.z);
                acc.w = fmaf(wv, xv.w, acc.w);
                accw += wv;
            }
        }

        // reduce over rg (lane bits 3,4); rows distinct per rg, duplicated
        // only across sub -> accw needs no correction.
        #pragma unroll
        for (int off = 8; off < 32; off <<= 1) {
            acc.x += __shfl_xor_sync(0xFFFFFFFFu, acc.x, off);
            acc.y += __shfl_xor_sync(0xFFFFFFFFu, acc.y, off);
            acc.z += __shfl_xor_sync(0xFFFFFFFFu, acc.z, off);
            acc.w += __shfl_xor_sync(0xFFFFFFFFu, acc.w, off);
            accw  += __shfl_xor_sync(0xFFFFFFFFu, accw,  off);
        }
        if (lane < 8)  sh4[warp][lane] = acc;
        if (lane == 0) shw[warp] = accw;
    }
    __syncthreads();

    if (tid < 32) {
        float v = 0.f;
        #pragma unroll
        for (int q = 0; q < NWARP; ++q)
            v += reinterpret_cast<const float*>(&sh4[q][tid >> 2])[tid & 3];
        g_part[tid * NBLK + blockIdx.x] = v;
    } else if (tid == 32) {
        float v = 0.f;
        #pragma unroll
        for (int q = 0; q < NWARP; ++q) v += shw[q];
        g_part[32 * NBLK + blockIdx.x] = v;
    }
    if (tid < 33) __threadfence();     // push g_part to L2 before arriving
    __syncthreads();

    // ---------------- grid barrier (replay-safe) ----------------
    if (tid == 0) {
        sh_r0 = *(volatile int*)&g_release;
        __threadfence();
        int t = atomicAdd(&g_arrive, 1);
        sh_last = (t == NBLK - 1);
    }
    __syncthreads();

    if (sh_last) {
        // ---------------- Phase B: finish reduce + tiny MLP ----------------
        {   // cols 0..31: 8 sub-reducers each (all 256 threads)
            int c = tid >> 3, k = tid & 7;
            float a = 0.f;
            #pragma unroll 4
            for (int b = k; b < NBLK; b += 8)
                a += __ldcg(&g_part[c * NBLK + b]);
            red[c][k] = a;
        }
        if (tid < 8) {  // col 32 (sum of weights)
            float a = 0.f;
            #pragma unroll 4
            for (int b = tid; b < NBLK; b += 8)
                a += __ldcg(&g_part[32 * NBLK + b]);
            red[32][tid] = a;
        }
        __syncthreads();
        if (tid < 33) {
            float a = 0.f;
            #pragma unroll
            for (int k = 0; k < 8; ++k) a += red[tid][k];
            s_[tid] = a;
        }
        __syncthreads();
        if (tid < 128) {
            float inv = 1.f / s_[32];
            float d = 0.f;
            #pragma unroll
            for (int i = 0; i < 32; ++i) d = fmaf(s_[i], Win[tid * 32 + i], d);
            h_[tid] = fmaxf(d * inv, 0.f);
        }
        __syncthreads();
        if (tid < 32) {
            float d = 0.f;
            #pragma unroll
            for (int j = 0; j < 128; ++j) d = fmaf(h_[j], Wout[tid * 128 + j], d);
            g_res[tid] = d;
            __threadfence();
        }
        __syncthreads();
        if (tid == 0) {
            g_arrive = 0;                      // reset for next graph replay
            __threadfence();
            atomicAdd(&g_release, 1);          // monotone release
        }
    } else {
        if (tid == 0) {
            while (*(volatile int*)&g_release == sh_r0) __nanosleep(64);
        }
        __syncthreads();
        __threadfence();
    }

    // ---------------- Phase C: out = x + broadcast(x_) ----------------
    // LIFO over the SAME rows this block reduced in phase A; evict-first
    // loads (last use) and stores (don't pollute L2 for other blocks).
    if (tid < 8) r4s[tid] = __ldcg(reinterpret_cast<const float4*>(g_res) + tid);
    __syncthreads();

    {
        const float4* __restrict__ xr = reinterpret_cast<const float4*>(x);
        float4* __restrict__ ow       = reinterpret_cast<float4*>(out);
        const int n4     = N * 8;
        const int chunkC = R * NWARP * 8;                   // same rows as phase A
        const int start  = blockIdx.x * chunkC;
        const int end    = min(start + chunkC, n4);
        const int count  = max(end - start, 0);
        const int nFull  = count / TPB;
        const int rem    = count - nFull * TPB;

        const float4 rv = r4s[tid & 7];   // i%8 == tid%8 (start, TPB mult of 8)

        // partial strip (highest addresses) first
        if (rem && tid < rem) {
            int i = start + nFull * TPB + tid;
            float4 v = __ldcs(&xr[i]);
            v.x += rv.x; v.y += rv.y; v.z += rv.z; v.w += rv.w;
            __stcs(&ow[i], v);
        }

        int k = nFull;
        for (; k >= 8; k -= 8) {
            int ib = start + (k - 8) * TPB + tid;
            float4 v0 = __ldcs(&xr[ib + 7 * TPB]);
            float4 v1 = __ldcs(&xr[ib + 6 * TPB]);
            float4 v2 = __ldcs(&xr[ib + 5 * TPB]);
            float4 v3 = __ldcs(&xr[ib + 4 * TPB]);
            float4 v4 = __ldcs(&xr[ib + 3 * TPB]);
            float4 v5 = __ldcs(&xr[ib + 2 * TPB]);
            float4 v6 = __ldcs(&xr[ib + 1 * TPB]);
            float4 v7 = __ldcs(&xr[ib + 0 * TPB]);
            v0.x += rv.x; v0.y += rv.y; v0.z += rv.z; v0.w += rv.w;
            v1.x += rv.x; v1.y += rv.y; v1.z += rv.z; v1.w += rv.w;
            v2.x += rv.x; v2.y += rv.y; v2.z += rv.z; v2.w += rv.w;
            v3.x += rv.x; v3.y += rv.y; v3.z += rv.z; v3.w += rv.w;
            v4.x += rv.x; v4.y += rv.y; v4.z += rv.z; v4.w += rv.w;
            v5.x += rv.x; v5.y += rv.y; v5.z += rv.z; v5.w += rv.w;
            v6.x += rv.x; v6.y += rv.y; v6.z += rv.z; v6.w += rv.w;
            v7.x += rv.x; v7.y += rv.y; v7.z += rv.z; v7.w += rv.w;
            __stcs(&ow[ib + 7 * TPB], v0);
            __stcs(&ow[ib + 6 * TPB], v1);
            __stcs(&ow[ib + 5 * TPB], v2);
            __stcs(&ow[ib + 4 * TPB], v3);
            __stcs(&ow[ib + 3 * TPB], v4);
            __stcs(&ow[ib + 2 * TPB], v5);
            __stcs(&ow[ib + 1 * TPB], v6);
            __stcs(&ow[ib + 0 * TPB], v7);
        }
        for (; k >= 1; --k) {
            int i = start + (k - 1) * TPB + tid;
            float4 v = __ldcs(&xr[i]);
            v.x += rv.x; v.y += rv.y; v.z += rv.z; v.w += rv.w;
            __stcs(&ow[i], v);
        }
    }
}

extern "C" void kernel_launch(void* const* d_in, const int* in_sizes, int n_in,
                              void* d_out, int out_size)
{
    const float* x    = (const float*)d_in[0];   // [N,32]
    const float* w    = (const float*)d_in[1];   // [N,1]
    const float* Win  = (const float*)d_in[2];   // [128,32]
    const float* Wout = (const float*)d_in[3];   // [32,128]
    float* out        = (float*)d_out;           // [N,32]

    const int N = in_sizes[1];                   // 1,000,000

    fused_kernel<<<NBLK, TPB>>>(x, w, Win, Wout, out, N);
}

// round 13
// speedup vs baseline: 1.0893x; 1.0056x over previous
#include <cuda_runtime.h>
#include <cuda_bf16.h>

// ResidualAverageBlock, fused persistent kernel with tile work-stealing.
//   Phase A: per-512-row-tile partials s_t[32], sw_t (deterministic per tile)
//   grid-barrier (replay-safe, monotone release)
//   Phase B (last block): fixed-order tile reduce -> h = relu((s@Win^T)/sw),
//                         x_ = h@Wout^T
//   Phase C (all blocks): out = x + broadcast(x_), stealing tiles in
//                         DESCENDING order (global LIFO -> L2 hits on x).

#define NBLK   608                 // 4 per SM x 152 SMs (all co-resident)
#define TPB    256
#define NWARP  8
#define TROWS  512                 // rows per tile (64 rows per warp)
#define NTP    2048                // padded tile stride (zero-init tail)

__device__ __align__(16) float g_part[33 * NTP];   // [c][tile], zero-init
__device__ float g_res[32];
__device__ int   g_cntA   = 0;     // phase-A tile counter (reset by master)
__device__ int   g_cntC   = 0;     // phase-C tile counter (reset by master)
__device__ int   g_arrive = 0;     // barrier arrivals (reset by master)
__device__ int   g_release = 0;    // monotone across graph replays

__global__ __launch_bounds__(TPB, 4)
void fused_kernel(const float* __restrict__ x, const float* __restrict__ w,
                  const float* __restrict__ Win, const float* __restrict__ Wout,
                  float* __restrict__ out, int N)
{
    const int tid  = threadIdx.x;
    const int lane = tid & 31;
    const int warp = tid >> 5;
    const int sub  = lane & 7;     // column group: cols 4*sub .. 4*sub+3
    const int rg   = lane >> 3;    // row group within warp

    const int NT = (N + TROWS - 1) / TROWS;          // 1954 tiles

    __shared__ float4 sh4[NWARP][8];
    __shared__ float  shw[NWARP];
    __shared__ float  red[33][8];
    __shared__ float  red32[8];
    __shared__ float  s_[33];
    __shared__ float  h_[128];
    __shared__ float4 r4s[8];
    __shared__ int    sh_next, sh_last, sh_r0;

    const float4* __restrict__ x4 = reinterpret_cast<const float4*>(x);
    const float4* __restrict__ w4 = reinterpret_cast<const float4*>(w);

    // ================= Phase A: steal tiles, per-tile partials ==============
    if (tid == 0) sh_next = atomicAdd(&g_cntA, 1);
    __syncthreads();
    int cur = sh_next;
    while (cur < NT) {
        __syncthreads();                         // everyone has cur in reg
        if (tid == 0) sh_next = atomicAdd(&g_cntA, 1);   // prefetch next tile

        const int base = cur * TROWS;
        int row        = base + warp * 64;       // row % 64 == 0 always
        const int rend = min(row + 64, N);

        float4 acc = make_float4(0.f, 0.f, 0.f, 0.f);
        float  accw = 0.f;

        // 32 rows/iter; thread (rg,sub) owns rows row+4rg..+3 and row+16+4rg..+3,
        // cols 4sub..4sub+3. All 10 loads LDG.128, front-batchable.
        for (; row + 32 <= rend; row += 32) {
            const int rb = row >> 2;             // exact: row % 4 == 0
            float4 wa = __ldg(&w4[rb + rg]);
            float4 wb = __ldg(&w4[rb + 4 + rg]);
            float4 xv0 = __ldg(&x4[(row +      4*rg + 0) * 8 + sub]);
            float4 xv1 = __ldg(&x4[(row +      4*rg + 1) * 8 + sub]);
            float4 xv2 = __ldg(&x4[(row +      4*rg + 2) * 8 + sub]);
            float4 xv3 = __ldg(&x4[(row +      4*rg + 3) * 8 + sub]);
            float4 xv4 = __ldg(&x4[(row + 16 + 4*rg + 0) * 8 + sub]);
            float4 xv5 = __ldg(&x4[(row + 16 + 4*rg + 1) * 8 + sub]);
            float4 xv6 = __ldg(&x4[(row + 16 + 4*rg + 2) * 8 + sub]);
            float4 xv7 = __ldg(&x4[(row + 16 + 4*rg + 3) * 8 + sub]);

            acc.x = fmaf(wa.x, xv0.x, acc.x); acc.y = fmaf(wa.x, xv0.y, acc.y);
            acc.z = fmaf(wa.x, xv0.z, acc.z); acc.w = fmaf(wa.x, xv0.w, acc.w);
            acc.x = fmaf(wa.y, xv1.x, acc.x); acc.y = fmaf(wa.y, xv1.y, acc.y);
            acc.z = fmaf(wa.y, xv1.z, acc.z); acc.w = fmaf(wa.y, xv1.w, acc.w);
            acc.x = fmaf(wa.z, xv2.x, acc.x); acc.y = fmaf(wa.z, xv2.y, acc.y);
            acc.z = fmaf(wa.z, xv2.z, acc.z); acc.w = fmaf(wa.z, xv2.w, acc.w);
            acc.x = fmaf(wa.w, xv3.x, acc.x); acc.y = fmaf(wa.w, xv3.y, acc.y);
            acc.z = fmaf(wa.w, xv3.z, acc.z); acc.w = fmaf(wa.w, xv3.w, acc.w);
            acc.x = fmaf(wb.x, xv4.x, acc.x); acc.y = fmaf(wb.x, xv4.y, acc.y);
            acc.z = fmaf(wb.x, xv4.z, acc.z); acc.w = fmaf(wb.x, xv4.w, acc.w);
            acc.x = fmaf(wb.y, xv5.x, acc.x); acc.y = fmaf(wb.y, xv5.y, acc.y);
            acc.z = fmaf(wb.y, xv5.z, acc.z); acc.w = fmaf(wb.y, xv5.w, acc.w);
            acc.x = fmaf(wb.z, xv6.x, acc.x); acc.y = fmaf(wb.z, xv6.y, acc.y);
            acc.z = fmaf(wb.z, xv6.z, acc.z); acc.w = fmaf(wb.z, xv6.w, acc.w);
            acc.x = fmaf(wb.w, xv7.x, acc.x); acc.y = fmaf(wb.w, xv7.y, acc.y);
            acc.z = fmaf(wb.w, xv7.z, acc.z); acc.w = fmaf(wb.w, xv7.w, acc.w);

            accw += ((wa.x + wa.y) + (wa.z + wa.w))
                  + ((wb.x + wb.y) + (wb.z + wb.w));
        }
        // tail (scalar w loads, alignment-free)
        for (; row < rend; row += 4) {
            int rr = row + rg;
            if (rr < rend) {
                float  wv = __ldg(&w[rr]);
                float4 xv = __ldg(&x4[rr * 8 + sub]);
                acc.x = fmaf(wv, xv.x, acc.x);
                acc.y = fmaf(wv, xv.y, acc.y);
                acc.z = fmaf(wv, xv.z, acc.z);
                acc.w = fmaf(wv, xv.w, acc.w);
                accw += wv;
            }
        }

        // reduce over rg (lane bits 3,4); rows distinct per rg, duplicated
        // only across sub -> accw needs no correction.
        #pragma unroll
        for (int off = 8; off < 32; off <<= 1) {
            acc.x += __shfl_xor_sync(0xFFFFFFFFu, acc.x, off);
            acc.y += __shfl_xor_sync(0xFFFFFFFFu, acc.y, off);
            acc.z += __shfl_xor_sync(0xFFFFFFFFu, acc.z, off);
            acc.w += __shfl_xor_sync(0xFFFFFFFFu, acc.w, off);
            accw  += __shfl_xor_sync(0xFFFFFFFFu, accw,  off);
        }
        if (lane < 8)  sh4[warp][lane] = acc;
        if (lane == 0) shw[warp] = accw;
        __syncthreads();

        // per-TILE partial: deterministic regardless of which block ran it
        if (tid < 32) {
            float v = 0.f;
            #pragma unroll
            for (int q = 0; q < NWARP; ++q)
                v += reinterpret_cast<const float*>(&sh4[q][tid >> 2])[tid & 3];
            g_part[tid * NTP + cur] = v;
        } else if (tid == 32) {
            float v = 0.f;
            #pragma unroll
            for (int q = 0; q < NWARP; ++q) v += shw[q];
            g_part[32 * NTP + cur] = v;
        }
        __syncthreads();                         // sh4/shw + sh_next ready
        cur = sh_next;
    }
    __threadfence();                             // publish g_part before arrive

    // ================= grid barrier (replay-safe) ===========================
    if (tid == 0) {
        sh_r0 = *(volatile int*)&g_release;
        __threadfence();
        int t = atomicAdd(&g_arrive, 1);
        sh_last = (t == NBLK - 1);
    }
    __syncthreads();

    if (sh_last) {
        // ============ Phase B: fixed-order tile reduce + tiny MLP ===========
        const int F4 = (NT + 3) >> 2;            // float4 count per column
        const int FB = (F4 + 7) & ~7;            // padded bound (zeros beyond NT)
        {
            int c = tid >> 3, k = tid & 7;       // cols 0..31, 8 reducers each
            const float4* P4 = reinterpret_cast<const float4*>(g_part + c * NTP);
            float4 a = make_float4(0.f, 0.f, 0.f, 0.f);
            #pragma unroll 4
            for (int j = k; j < FB; j += 8) {
                float4 v = __ldcg(&P4[j]);
                a.x += v.x; a.y += v.y; a.z += v.z; a.w += v.w;
            }
            red[c][k] = (a.x + a.y) + (a.z + a.w);
        }
        if (tid < 8) {                            // col 32 (sum of weights)
            const float4* P4 = reinterpret_cast<const float4*>(g_part + 32 * NTP);
            float4 a = make_float4(0.f, 0.f, 0.f, 0.f);
            #pragma unroll 4
            for (int j = tid; j < FB; j += 8) {
                float4 v = __ldcg(&P4[j]);
                a.x += v.x; a.y += v.y; a.z += v.z; a.w += v.w;
            }
            red32[tid] = (a.x + a.y) + (a.z + a.w);
        }
        __syncthreads();
        if (tid < 32) {
            float a = 0.f;
            #pragma unroll
            for (int k = 0; k < 8; ++k) a += red[tid][k];
            s_[tid] = a;
        } else if (tid == 32) {
            float a = 0.f;
            #pragma unroll
            for (int k = 0; k < 8; ++k) a += red32[k];
            s_[32] = a;
        }
        __syncthreads();
        if (tid < 128) {
            float inv = 1.f / s_[32];
            float d = 0.f;
            #pragma unroll
            for (int i = 0; i < 32; ++i) d = fmaf(s_[i], Win[tid * 32 + i], d);
            h_[tid] = fmaxf(d * inv, 0.f);
        }
        __syncthreads();
        if (tid < 32) {
            float d = 0.f;
            #pragma unroll
            for (int j = 0; j < 128; ++j) d = fmaf(h_[j], Wout[tid * 128 + j], d);
            g_res[tid] = d;
            __threadfence();
        }
        __syncthreads();
        if (tid == 0) {
            g_arrive = 0;                        // reset for next replay
            g_cntA   = 0;
            g_cntC   = 0;                        // phase C of THIS run starts at 0
            __threadfence();
            atomicAdd(&g_release, 1);            // monotone release
        }
    } else {
        if (tid == 0) {
            while (*(volatile int*)&g_release == sh_r0) __nanosleep(64);
        }
        __syncthreads();
        __threadfence();
    }

    // ============ Phase C: out = x + broadcast(x_), LIFO tile stealing ======
    if (tid < 8) r4s[tid] = __ldcg(reinterpret_cast<const float4*>(g_res) + tid);
    __syncthreads();

    {
        const float4* __restrict__ xr = reinterpret_cast<const float4*>(x);
        float4* __restrict__ ow       = reinterpret_cast<float4*>(out);
        const int n4 = N * 8;
        const float4 rv = r4s[tid & 7];          // tile base, TPB mult of 8

        if (tid == 0) sh_next = atomicAdd(&g_cntC, 1);
        __syncthreads();
        int t = sh_next;
        while (t < NT) {
            __syncthreads();
            if (tid == 0) sh_next = atomicAdd(&g_cntC, 1);

            const int tc = NT - 1 - t;           // descending = global LIFO
            const int f0 = tc * (TROWS * 8);
            const int f1 = min(f0 + TROWS * 8, n4);

            if (f1 - f0 == TROWS * 8) {
                int i = f0 + tid;
                #pragma unroll
                for (int b = 0; b < 2; ++b) {    // 2 x 8-batch = 16 f4/thread
                    float4 v0 = __ldcs(&xr[i + 0 * TPB]);
                    float4 v1 = __ldcs(&xr[i + 1 * TPB]);
                    float4 v2 = __ldcs(&xr[i + 2 * TPB]);
                    float4 v3 = __ldcs(&xr[i + 3 * TPB]);
                    float4 v4 = __ldcs(&xr[i + 4 * TPB]);
                    float4 v5 = __ldcs(&xr[i + 5 * TPB]);
                    float4 v6 = __ldcs(&xr[i + 6 * TPB]);
                    float4 v7 = __ldcs(&xr[i + 7 * TPB]);
                    v0.x += rv.x; v0.y += rv.y; v0.z += rv.z; v0.w += rv.w;
                    v1.x += rv.x; v1.y += rv.y; v1.z += rv.z; v1.w += rv.w;
                    v2.x += rv.x; v2.y += rv.y; v2.z += rv.z; v2.w += rv.w;
                    v3.x += rv.x; v3.y += rv.y; v3.z += rv.z; v3.w += rv.w;
                    v4.x += rv.x; v4.y += rv.y; v4.z += rv.z; v4.w += rv.w;
                    v5.x += rv.x; v5.y += rv.y; v5.z += rv.z; v5.w += rv.w;
                    v6.x += rv.x; v6.y += rv.y; v6.z += rv.z; v6.w += rv.w;
                    v7.x += rv.x; v7.y += rv.y; v7.z += rv.z; v7.w += rv.w;
                    __stcs(&ow[i + 0 * TPB], v0);
                    __stcs(&ow[i + 1 * TPB], v1);
                    __stcs(&ow[i + 2 * TPB], v2);
                    __stcs(&ow[i + 3 * TPB], v3);
                    __stcs(&ow[i + 4 * TPB], v4);
                    __stcs(&ow[i + 5 * TPB], v5);
                    __stcs(&ow[i + 6 * TPB], v6);
                    __stcs(&ow[i + 7 * TPB], v7);
                    i += 8 * TPB;
                }
            } else {
                for (int i = f0 + tid; i < f1; i += TPB) {
                    float4 v = __ldcs(&xr[i]);
                    v.x += rv.x; v.y += rv.y; v.z += rv.z; v.w += rv.w;
                    __stcs(&ow[i], v);
                }
            }
            __syncthreads();                     // sh_next consumed next iter
            t = sh_next;
        }
    }
}

extern "C" void kernel_launch(void* const* d_in, const int* in_sizes, int n_in,
                              void* d_out, int out_size)
{
    const float* x    = (const float*)d_in[0];   // [N,32]
    const float* w    = (const float*)d_in[1];   // [N,1]
    const float* Win  = (const float*)d_in[2];   // [128,32]
    const float* Wout = (const float*)d_in[3];   // [32,128]
    float* out        = (float*)d_out;           // [N,32]

    const int N = in_sizes[1];                   // 1,000,000

    fused_kernel<<<NBLK, TPB>>>(x, w, Win, Wout, out, N);
}

// round 15
// speedup vs baseline: 1.1418x; 1.0483x over previous
#include <cuda_runtime.h>
#include <cuda_bf16.h>

// ResidualAverageBlock, fused persistent kernel (static partition, high-reg).
//   Phase A: s[32] = sum_n w_n * x_n ; sw = sum_n w_n  (per-block partials,
//            64-row iterations, 20 LDG.128 front-batched per warp)
//   grid-barrier (replay-safe, monotone release)
//   Phase B (last block): h = relu((s@Win^T)/sw); x_ = h@Wout^T
//   Phase C (all blocks): out = x + broadcast(x_), even split, LIFO within
//            block chunk, evict-first loads/stores.

#define NBLK  304                          // 2 per SM x 152 SMs
#define TPB   256
#define NWARP 8
#define TOTW  (NBLK * NWARP)               // 2432

__device__ float g_part[33 * NBLK];        // [c][b]
__device__ float g_res[32];
__device__ int   g_arrive  = 0;            // reset by master each run
__device__ int   g_release = 0;            // monotone across graph replays

__global__ __launch_bounds__(TPB, 2)       // 128-reg budget: real 20-load batches
void fused_kernel(const float* __restrict__ x, const float* __restrict__ w,
                  const float* __restrict__ Win, const float* __restrict__ Wout,
                  float* __restrict__ out, int N)
{
    const int tid  = threadIdx.x;
    const int lane = tid & 31;
    const int warp = tid >> 5;
    const int sub  = lane & 7;     // column group: cols 4*sub .. 4*sub+3
    const int rg   = lane >> 3;    // row group within warp

    __shared__ float4 sh4[NWARP][8];
    __shared__ float  shw[NWARP];
    __shared__ float  red[33][8];
    __shared__ float  s_[33];
    __shared__ float  h_[128];
    __shared__ float4 r4s[8];
    __shared__ int    sh_last, sh_r0;

    // rows per warp, rounded to 32 so every warp's start row % 32 == 0
    const int R = ((N + TOTW - 1) / TOTW + 31) & ~31;     // 416 for N=1e6

    // ================= Phase A: weighted column reduce ======================
    {
        const float4* __restrict__ x4 = reinterpret_cast<const float4*>(x);
        const float4* __restrict__ w4 = reinterpret_cast<const float4*>(w);
        const int gw = blockIdx.x * NWARP + warp;
        int row      = gw * R;                            // multiple of 32
        const int r1 = min(row + R, N);

        float4 acc = make_float4(0.f, 0.f, 0.f, 0.f);
        float  accw = 0.f;

        // ---- 64 rows / iteration: 4 w-LDG.128 + 16 x-LDG.128, ALL loads
        //      issued before any FMA (needs the 128-reg budget). Thread
        //      (rg,sub) owns rows base+16k+4rg+j (j=0..3), cols 4sub..4sub+3.
        for (; row + 64 <= r1; row += 64) {
            const int rb = row >> 2;                      // exact: row%4==0
            float4 wv[4];
            #pragma unroll
            for (int k = 0; k < 4; ++k)
                wv[k] = __ldg(&w4[rb + 4 * k + rg]);
            float4 xv[16];
            #pragma unroll
            for (int k = 0; k < 4; ++k)
                #pragma unroll
                for (int j = 0; j < 4; ++j)
                    xv[k * 4 + j] =
                        __ldg(&x4[(row + 16 * k + 4 * rg + j) * 8 + sub]);

            #pragma unroll
            for (int k = 0; k < 4; ++k) {
                acc.x = fmaf(wv[k].x, xv[k*4+0].x, acc.x);
                acc.y = fmaf(wv[k].x, xv[k*4+0].y, acc.y);
                acc.z = fmaf(wv[k].x, xv[k*4+0].z, acc.z);
                acc.w = fmaf(wv[k].x, xv[k*4+0].w, acc.w);
                acc.x = fmaf(wv[k].y, xv[k*4+1].x, acc.x);
                acc.y = fmaf(wv[k].y, xv[k*4+1].y, acc.y);
                acc.z = fmaf(wv[k].y, xv[k*4+1].z, acc.z);
                acc.w = fmaf(wv[k].y, xv[k*4+1].w, acc.w);
                acc.x = fmaf(wv[k].z, xv[k*4+2].x, acc.x);
                acc.y = fmaf(wv[k].z, xv[k*4+2].y, acc.y);
                acc.z = fmaf(wv[k].z, xv[k*4+2].z, acc.z);
                acc.w = fmaf(wv[k].z, xv[k*4+2].w, acc.w);
                acc.x = fmaf(wv[k].w, xv[k*4+3].x, acc.x);
                acc.y = fmaf(wv[k].w, xv[k*4+3].y, acc.y);
                acc.z = fmaf(wv[k].w, xv[k*4+3].z, acc.z);
                acc.w = fmaf(wv[k].w, xv[k*4+3].w, acc.w);
                accw += ((wv[k].x + wv[k].y) + (wv[k].z + wv[k].w));
            }
        }
        // ---- 32-row leftover (start still %32==0)
        for (; row + 32 <= r1; row += 32) {
            const int rb = row >> 2;
            float4 wa = __ldg(&w4[rb + rg]);
            float4 wb = __ldg(&w4[rb + 4 + rg]);
            float4 xv[8];
            #pragma unroll
            for (int j = 0; j < 4; ++j) {
                xv[j]     = __ldg(&x4[(row +      4*rg + j) * 8 + sub]);
                xv[4 + j] = __ldg(&x4[(row + 16 + 4*rg + j) * 8 + sub]);
            }
            const float wlo[4] = {wa.x, wa.y, wa.z, wa.w};
            const float whi[4] = {wb.x, wb.y, wb.z, wb.w};
            #pragma unroll
            for (int j = 0; j < 4; ++j) {
                acc.x = fmaf(wlo[j], xv[j].x, acc.x);
                acc.y = fmaf(wlo[j], xv[j].y, acc.y);
                acc.z = fmaf(wlo[j], xv[j].z, acc.z);
                acc.w = fmaf(wlo[j], xv[j].w, acc.w);
                acc.x = fmaf(whi[j], xv[4+j].x, acc.x);
                acc.y = fmaf(whi[j], xv[4+j].y, acc.y);
                acc.z = fmaf(whi[j], xv[4+j].z, acc.z);
                acc.w = fmaf(whi[j], xv[4+j].w, acc.w);
            }
            accw += ((wa.x + wa.y) + (wa.z + wa.w))
                  + ((wb.x + wb.y) + (wb.z + wb.w));
        }
        // ---- scalar tail (N edge)
        for (; row < r1; row += 4) {
            int rr = row + rg;
            if (rr < r1) {
                float  wv = __ldg(&w[rr]);
                float4 xv = __ldg(&x4[rr * 8 + sub]);
                acc.x = fmaf(wv, xv.x, acc.x);
                acc.y = fmaf(wv, xv.y, acc.y);
                acc.z = fmaf(wv, xv.z, acc.z);
                acc.w = fmaf(wv, xv.w, acc.w);
                accw += wv;
            }
        }

        // reduce over rg (lane bits 3,4); rows distinct per rg, duplicated
        // only across sub -> accw needs no correction.
        #pragma unroll
        for (int off = 8; off < 32; off <<= 1) {
            acc.x += __shfl_xor_sync(0xFFFFFFFFu, acc.x, off);
            acc.y += __shfl_xor_sync(0xFFFFFFFFu, acc.y, off);
            acc.z += __shfl_xor_sync(0xFFFFFFFFu, acc.z, off);
            acc.w += __shfl_xor_sync(0xFFFFFFFFu, acc.w, off);
            accw  += __shfl_xor_sync(0xFFFFFFFFu, accw,  off);
        }
        if (lane < 8)  sh4[warp][lane] = acc;
        if (lane == 0) shw[warp] = accw;
    }
    __syncthreads();

    if (tid < 32) {
        float v = 0.f;
        #pragma unroll
        for (int q = 0; q < NWARP; ++q)
            v += reinterpret_cast<const float*>(&sh4[q][tid >> 2])[tid & 3];
        g_part[tid * NBLK + blockIdx.x] = v;
    } else if (tid == 32) {
        float v = 0.f;
        #pragma unroll
        for (int q = 0; q < NWARP; ++q) v += shw[q];
        g_part[32 * NBLK + blockIdx.x] = v;
    }
    if (tid < 33) __threadfence();     // publish g_part before arriving
    __syncthreads();

    // ================= grid barrier (replay-safe) ===========================
    if (tid == 0) {
        sh_r0 = *(volatile int*)&g_release;
        __threadfence();
        int t = atomicAdd(&g_arrive, 1);
        sh_last = (t == NBLK - 1);
    }
    __syncthreads();

    if (sh_last) {
        // ============ Phase B: finish reduce + tiny MLP =====================
        {   // cols 0..31: 8 sub-reducers each (all 256 threads)
            int c = tid >> 3, k = tid & 7;
            float a = 0.f;
            #pragma unroll 4
            for (int b = k; b < NBLK; b += 8)
                a += __ldcg(&g_part[c * NBLK + b]);
            red[c][k] = a;
        }
        if (tid < 8) {  // col 32 (sum of weights)
            float a = 0.f;
            #pragma unroll 4
            for (int b = tid; b < NBLK; b += 8)
                a += __ldcg(&g_part[32 * NBLK + b]);
            red[32][tid] = a;
        }
        __syncthreads();
        if (tid < 33) {
            float a = 0.f;
            #pragma unroll
            for (int k = 0; k < 8; ++k) a += red[tid][k];
            s_[tid] = a;
        }
        __syncthreads();
        if (tid < 128) {
            float inv = 1.f / s_[32];
            float d = 0.f;
            #pragma unroll
            for (int i = 0; i < 32; ++i) d = fmaf(s_[i], Win[tid * 32 + i], d);
            h_[tid] = fmaxf(d * inv, 0.f);
        }
        __syncthreads();
        if (tid < 32) {
            float d = 0.f;
            #pragma unroll
            for (int j = 0; j < 128; ++j) d = fmaf(h_[j], Wout[tid * 128 + j], d);
            g_res[tid] = d;
            __threadfence();
        }
        __syncthreads();
        if (tid == 0) {
            g_arrive = 0;                      // reset for next replay
            __threadfence();
            atomicAdd(&g_release, 1);          // monotone release
        }
    } else {
        if (tid == 0) {
            while (*(volatile int*)&g_release == sh_r0) __nanosleep(64);
        }
        __syncthreads();
        __threadfence();
    }

    // ============ Phase C: out = x + broadcast(x_) ==========================
    // Even split over all blocks (decoupled from phase A's rounded split),
    // LIFO within chunk; evict-first loads (L2-resident x) and stores.
    if (tid < 8) r4s[tid] = __ldcg(reinterpret_cast<const float4*>(g_res) + tid);
    __syncthreads();

    {
        const float4* __restrict__ xr = reinterpret_cast<const float4*>(x);
        float4* __restrict__ ow       = reinterpret_cast<float4*>(out);
        const int n4     = N * 8;
        const int chunkC = (((n4 + NBLK - 1) / NBLK) + 7) & ~7;  // %8 == 0
        const int start  = blockIdx.x * chunkC;
        const int end    = min(start + chunkC, n4);
        const int count  = max(end - start, 0);
        const int nFull  = count / TPB;
        const int rem    = count - nFull * TPB;

        const float4 rv = r4s[tid & 7];   // i%8 == tid%8 (start, TPB mult of 8)

        if (rem && tid < rem) {           // partial strip (highest addrs) first
            int i = start + nFull * TPB + tid;
            float4 v = __ldcs(&xr[i]);
            v.x += rv.x; v.y += rv.y; v.z += rv.z; v.w += rv.w;
            __stcs(&ow[i], v);
        }

        int k = nFull;
        for (; k >= 8; k -= 8) {
            int ib = start + (k - 8) * TPB + tid;
            float4 v0 = __ldcs(&xr[ib + 7 * TPB]);
            float4 v1 = __ldcs(&xr[ib + 6 * TPB]);
            float4 v2 = __ldcs(&xr[ib + 5 * TPB]);
            float4 v3 = __ldcs(&xr[ib + 4 * TPB]);
            float4 v4 = __ldcs(&xr[ib + 3 * TPB]);
            float4 v5 = __ldcs(&xr[ib + 2 * TPB]);
            float4 v6 = __ldcs(&xr[ib + 1 * TPB]);
            float4 v7 = __ldcs(&xr[ib + 0 * TPB]);
            v0.x += rv.x; v0.y += rv.y; v0.z += rv.z; v0.w += rv.w;
            v1.x += rv.x; v1.y += rv.y; v1.z += rv.z; v1.w += rv.w;
            v2.x += rv.x; v2.y += rv.y; v2.z += rv.z; v2.w += rv.w;
            v3.x += rv.x; v3.y += rv.y; v3.z += rv.z; v3.w += rv.w;
            v4.x += rv.x; v4.y += rv.y; v4.z += rv.z; v4.w += rv.w;
            v5.x += rv.x; v5.y += rv.y; v5.z += rv.z; v5.w += rv.w;
            v6.x += rv.x; v6.y += rv.y; v6.z += rv.z; v6.w += rv.w;
            v7.x += rv.x; v7.y += rv.y; v7.z += rv.z; v7.w += rv.w;
            __stcs(&ow[ib + 7 * TPB], v0);
            __stcs(&ow[ib + 6 * TPB], v1);
            __stcs(&ow[ib + 5 * TPB], v2);
            __stcs(&ow[ib + 4 * TPB], v3);
            __stcs(&ow[ib + 3 * TPB], v4);
            __stcs(&ow[ib + 2 * TPB], v5);
            __stcs(&ow[ib + 1 * TPB], v6);
            __stcs(&ow[ib + 0 * TPB], v7);
        }
        for (; k >= 1; --k) {
            int i = start + (k - 1) * TPB + tid;
            float4 v = __ldcs(&xr[i]);
            v.x += rv.x; v.y += rv.y; v.z += rv.z; v.w += rv.w;
            __stcs(&ow[i], v);
        }
    }
}

extern "C" void kernel_launch(void* const* d_in, const int* in_sizes, int n_in,
                              void* d_out, int out_size)
{
    const float* x    = (const float*)d_in[0];   // [N,32]
    const float* w    = (const float*)d_in[1];   // [N,1]
    const float* Win  = (const float*)d_in[2];   // [128,32]
    const float* Wout = (const float*)d_in[3];   // [32,128]
    float* out        = (float*)d_out;           // [N,32]

    const int N = in_sizes[1];                   // 1,000,000

    fused_kernel<<<NBLK, TPB>>>(x, w, Win, Wout, out, N);
}

// round 17
// speedup vs baseline: 1.1759x; 1.0298x over previous
#include <cuda_runtime.h>
#include <cuda_bf16.h>

// ResidualAverageBlock, fused persistent kernel (static partition, high-reg,
// double-buffered register pipelines in both streaming phases).
//   Phase A: s[32] = sum_n w_n * x_n ; sw = sum_n w_n  (per-block partials,
//            32-row chunks, ping-pong load/consume so loads never drain)
//   grid-barrier (replay-safe, monotone release)
//   Phase B (last block): h = relu((s@Win^T)/sw); x_ = h@Wout^T
//   Phase C (all blocks): out = x + broadcast(x_), even split, descending
//            chunk order (LIFO-ish for L2), ping-pong load/store,
//            evict-first loads/stores.

#define NBLK  304                          // 2 per SM x 152 SMs
#define TPB   256
#define NWARP 8
#define TOTW  (NBLK * NWARP)               // 2432

__device__ float g_part[33 * NBLK];        // [c][b]
__device__ float g_res[32];
__device__ int   g_arrive  = 0;            // reset by master each run
__device__ int   g_release = 0;            // monotone across graph replays

__global__ __launch_bounds__(TPB, 2)       // 128-reg budget for both buffers
void fused_kernel(const float* __restrict__ x, const float* __restrict__ w,
                  const float* __restrict__ Win, const float* __restrict__ Wout,
                  float* __restrict__ out, int N)
{
    const int tid  = threadIdx.x;
    const int lane = tid & 31;
    const int warp = tid >> 5;
    const int sub  = lane & 7;     // column group: cols 4*sub .. 4*sub+3
    const int rg   = lane >> 3;    // row group within warp

    __shared__ float4 sh4[NWARP][8];
    __shared__ float  shw[NWARP];
    __shared__ float  red[33][8];
    __shared__ float  s_[33];
    __shared__ float  h_[128];
    __shared__ float4 r4s[8];
    __shared__ int    sh_last, sh_r0;

    // rows per warp, rounded to 32 so every warp's start row % 32 == 0
    const int R = ((N + TOTW - 1) / TOTW + 31) & ~31;     // 416 for N=1e6

    // ================= Phase A: weighted column reduce ======================
    {
        const float4* __restrict__ x4 = reinterpret_cast<const float4*>(x);
        const float4* __restrict__ w4 = reinterpret_cast<const float4*>(w);
        const int gw = blockIdx.x * NWARP + warp;
        const int row0 = gw * R;                          // multiple of 32
        const int r1   = min(row0 + R, N);

        float4 acc = make_float4(0.f, 0.f, 0.f, 0.f);
        float  accw = 0.f;

        // one chunk = 32 rows: 2 w-LDG.128 + 8 x-LDG.128 (40 dest regs).
        // Two buffers ping-pong: next chunk's loads issued before current
        // chunk's FMAs -> load queue never drains inside the range.
        float4 bx[2][8];
        float4 bw[2][2];

        auto loadBuf = [&](int b, int r) {
            const int rb = r >> 2;                        // exact: r % 4 == 0
            bw[b][0] = __ldg(&w4[rb + rg]);
            bw[b][1] = __ldg(&w4[rb + 4 + rg]);
            #pragma unroll
            for (int j = 0; j < 4; ++j) {
                bx[b][j]     = __ldg(&x4[(r +      4*rg + j) * 8 + sub]);
                bx[b][4 + j] = __ldg(&x4[(r + 16 + 4*rg + j) * 8 + sub]);
            }
        };
        auto consume = [&](int b) {
            const float wl[4] = {bw[b][0].x, bw[b][0].y, bw[b][0].z, bw[b][0].w};
            const float wh[4] = {bw[b][1].x, bw[b][1].y, bw[b][1].z, bw[b][1].w};
            #pragma unroll
            for (int j = 0; j < 4; ++j) {
                acc.x = fmaf(wl[j], bx[b][j].x, acc.x);
                acc.y = fmaf(wl[j], bx[b][j].y, acc.y);
                acc.z = fmaf(wl[j], bx[b][j].z, acc.z);
                acc.w = fmaf(wl[j], bx[b][j].w, acc.w);
                acc.x = fmaf(wh[j], bx[b][4+j].x, acc.x);
                acc.y = fmaf(wh[j], bx[b][4+j].y, acc.y);
                acc.z = fmaf(wh[j], bx[b][4+j].z, acc.z);
                acc.w = fmaf(wh[j], bx[b][4+j].w, acc.w);
            }
            accw += ((bw[b][0].x + bw[b][0].y) + (bw[b][0].z + bw[b][0].w))
                  + ((bw[b][1].x + bw[b][1].y) + (bw[b][1].z + bw[b][1].w));
        };

        int r = row0;
        const int n = (r1 - r) / 32;       // full 32-row chunks (N%32==0 path)
        if (n > 0) {
            loadBuf(0, r);
            int i = 0;
            for (; i + 2 <= n; i += 2) {
                loadBuf(1, r + 32);        // chunk i+1 in flight
                consume(0);                // chunk i
                if (i + 2 < n) loadBuf(0, r + 64);   // chunk i+2 in flight
                consume(1);                // chunk i+1
                r += 64;
            }
            if (i < n) { consume(0); r += 32; }      // odd count: last chunk
        }
        // scalar tail (N edge; empty when N % 32 == 0)
        for (; r < r1; r += 4) {
            int rr = r + rg;
            if (rr < r1) {
                float  wv = __ldg(&w[rr]);
                float4 xv = __ldg(&x4[rr * 8 + sub]);
                acc.x = fmaf(wv, xv.x, acc.x);
                acc.y = fmaf(wv, xv.y, acc.y);
                acc.z = fmaf(wv, xv.z, acc.z);
                acc.w = fmaf(wv, xv.w, acc.w);
                accw += wv;
            }
        }

        // reduce over rg (lane bits 3,4); rows distinct per rg, duplicated
        // only across sub -> accw needs no correction.
        #pragma unroll
        for (int off = 8; off < 32; off <<= 1) {
            acc.x += __shfl_xor_sync(0xFFFFFFFFu, acc.x, off);
            acc.y += __shfl_xor_sync(0xFFFFFFFFu, acc.y, off);
            acc.z += __shfl_xor_sync(0xFFFFFFFFu, acc.z, off);
            acc.w += __shfl_xor_sync(0xFFFFFFFFu, acc.w, off);
            accw  += __shfl_xor_sync(0xFFFFFFFFu, accw,  off);
        }
        if (lane < 8)  sh4[warp][lane] = acc;
        if (lane == 0) shw[warp] = accw;
    }
    __syncthreads();

    if (tid < 32) {
        float v = 0.f;
        #pragma unroll
        for (int q = 0; q < NWARP; ++q)
            v += reinterpret_cast<const float*>(&sh4[q][tid >> 2])[tid & 3];
        g_part[tid * NBLK + blockIdx.x] = v;
    } else if (tid == 32) {
        float v = 0.f;
        #pragma unroll
        for (int q = 0; q < NWARP; ++q) v += shw[q];
        g_part[32 * NBLK + blockIdx.x] = v;
    }
    if (tid < 33) __threadfence();     // publish g_part before arriving
    __syncthreads();

    // ================= grid barrier (replay-safe) ===========================
    if (tid == 0) {
        sh_r0 = *(volatile int*)&g_release;
        __threadfence();
        int t = atomicAdd(&g_arrive, 1);
        sh_last = (t == NBLK - 1);
    }
    __syncthreads();

    if (sh_last) {
        // ============ Phase B: finish reduce + tiny MLP =====================
        {   // cols 0..31: 8 sub-reducers each (all 256 threads)
            int c = tid >> 3, k = tid & 7;
            float a = 0.f;
            #pragma unroll 4
            for (int b = k; b < NBLK; b += 8)
                a += __ldcg(&g_part[c * NBLK + b]);
            red[c][k] = a;
        }
        if (tid < 8) {  // col 32 (sum of weights)
            float a = 0.f;
            #pragma unroll 4
            for (int b = tid; b < NBLK; b += 8)
                a += __ldcg(&g_part[32 * NBLK + b]);
            red[32][tid] = a;
        }
        __syncthreads();
        if (tid < 33) {
            float a = 0.f;
            #pragma unroll
            for (int k = 0; k < 8; ++k) a += red[tid][k];
            s_[tid] = a;
        }
        __syncthreads();
        if (tid < 128) {
            float inv = 1.f / s_[32];
            float d = 0.f;
            #pragma unroll
            for (int i = 0; i < 32; ++i) d = fmaf(s_[i], Win[tid * 32 + i], d);
            h_[tid] = fmaxf(d * inv, 0.f);
        }
        __syncthreads();
        if (tid < 32) {
            float d = 0.f;
            #pragma unroll
            for (int j = 0; j < 128; ++j) d = fmaf(h_[j], Wout[tid * 128 + j], d);
            g_res[tid] = d;
            __threadfence();
        }
        __syncthreads();
        if (tid == 0) {
            g_arrive = 0;                      // reset for next replay
            __threadfence();
            atomicAdd(&g_release, 1);          // monotone release
        }
    } else {
        if (tid == 0) {
            while (*(volatile int*)&g_release == sh_r0) __nanosleep(64);
        }
        __syncthreads();
        __threadfence();
    }

    // ============ Phase C: out = x + broadcast(x_) ==========================
    // Even split; descending chunk order (recently-touched x lines first);
    // ping-pong buffers: next chunk's loads in flight during add+store.
    if (tid < 8) r4s[tid] = __ldcg(reinterpret_cast<const float4*>(g_res) + tid);
    __syncthreads();

    {
        const float4* __restrict__ xr = reinterpret_cast<const float4*>(x);
        float4* __restrict__ ow       = reinterpret_cast<float4*>(out);
        const int n4     = N * 8;
        const int chunkC = (((n4 + NBLK - 1) / NBLK) + 7) & ~7;  // %8 == 0
        const int start  = blockIdx.x * chunkC;
        const int end    = min(start + chunkC, n4);
        const int count  = max(end - start, 0);
        const int nFull  = count / TPB;                  // full strips
        const int rem    = count - nFull * TPB;
        const int m      = nFull / 8;                    // 8-strip chunks
        const int rem8   = nFull - m * 8;                // leftover strips (bottom)

        const float4 rv = r4s[tid & 7];   // i%8 == tid%8 (start, TPB mult of 8)

        float4 bc[2][8];
        auto loadChunk = [&](int b, int g) {
            const int base = start + (rem8 + g * 8) * TPB + tid;
            #pragma unroll
            for (int t = 0; t < 8; ++t) bc[b][t] = __ldcs(&xr[base + t * TPB]);
        };
        auto storeChunk = [&](int b, int g) {
            const int base = start + (rem8 + g * 8) * TPB + tid;
            #pragma unroll
            for (int t = 0; t < 8; ++t) {
                float4 v = bc[b][t];
                v.x += rv.x; v.y += rv.y; v.z += rv.z; v.w += rv.w;
                __stcs(&ow[base + t * TPB], v);
            }
        };

        // top partial strip first (highest addresses)
        if (rem && tid < rem) {
            int i = start + nFull * TPB + tid;
            float4 v = __ldcs(&xr[i]);
            v.x += rv.x; v.y += rv.y; v.z += rv.z; v.w += rv.w;
            __stcs(&ow[i], v);
        }

        // 8-strip chunks, descending, ping-pong
        if (m > 0) {
            loadChunk(0, m - 1);
            int i = 0;
            for (; i + 2 <= m; i += 2) {
                loadChunk(1, m - 2 - i);           // next chunk in flight
                storeChunk(0, m - 1 - i);
                if (i + 2 < m) loadChunk(0, m - 3 - i);
                storeChunk(1, m - 2 - i);
            }
            if (i < m) storeChunk(0, m - 1 - i);   // odd count
        }

        // leftover strips at the bottom, descending
        for (int s = rem8 - 1; s >= 0; --s) {
            int i = start + s * TPB + tid;
            float4 v = __ldcs(&xr[i]);
            v.x += rv.x; v.y += rv.y; v.z += rv.z; v.w += rv.w;
            __stcs(&ow[i], v);
        }
    }
}

extern "C" void kernel_launch(void* const* d_in, const int* in_sizes, int n_in,
                              void* d_out, int out_size)
{
    const float* x    = (const float*)d_in[0];   // [N,32]
    const float* w    = (const float*)d_in[1];   // [N,1]
    const float* Win  = (const float*)d_in[2];   // [128,32]
    const float* Wout = (const float*)d_in[3];   // [32,128]
    float* out        = (float*)d_out;           // [N,32]

    const int N = in_sizes[1];                   // 1,000,000

    fused_kernel<<<NBLK, TPB>>>(x, w, Win, Wout, out, N);
}